// round 8
// baseline (speedup 1.0000x reference)
#include <cuda_runtime.h>
#include <cuda_bf16.h>
#include <mma.h>
#include <math.h>

using namespace nvcuda;

// Problem constants (fixed by the dataset)
#define NROWS 20000
#define INF   1024
#define OUTF  64

// ---------------------------------------------------------------------------
// Scratch (device globals; no runtime allocation allowed)
// ---------------------------------------------------------------------------
__device__ alignas(256) float g_z0 [NROWS * OUTF];          // feat   @ W1
__device__ alignas(256) float g_za0[20064 * OUTF];          // feat_a @ W1 (padded: gemm1 tail rows)
__device__ alignas(256) float g_z2 [NROWS * OUTF];          // spmm(A, z)
__device__ alignas(256) float g_sa [NROWS * OUTF];          // spmm(A,  za0)
__device__ alignas(256) float g_ss [NROWS * OUTF];          // spmm(Aa, za0)

// ---------------------------------------------------------------------------
// fp32 -> bf16 hi/lo split (error-compensated tensor-core GEMM)
// ---------------------------------------------------------------------------
__device__ __forceinline__ void split_store(__nv_bfloat16* hi, __nv_bfloat16* lo, float x) {
    __nv_bfloat16 h = __float2bfloat16(x);
    *hi = h;
    *lo = __float2bfloat16(x - __bfloat162float(h));
}

// ---------------------------------------------------------------------------
// zero scratch that receives atomic scatter (+ z region of d_out)
// ---------------------------------------------------------------------------
__global__ void __launch_bounds__(256) zero_kernel(float* __restrict__ z_out) {
    int i = blockIdx.x * 256 + threadIdx.x;            // over 320000 float4 per array
    if (i < (NROWS * OUTF) / 4) {
        float4 z = make_float4(0.f, 0.f, 0.f, 0.f);
        reinterpret_cast<float4*>(z_out)[i] = z;
        reinterpret_cast<float4*>(g_sa)[i]  = z;
        reinterpret_cast<float4*>(g_ss)[i]  = z;
        reinterpret_cast<float4*>(g_z2)[i]  = z;
    }
}

// ---------------------------------------------------------------------------
// GEMM1: [40000,1024] @ [1024,64] -> z0 / za0   (feat rows 0..19999, feat_a rows 20000..39999)
// BM=128, BN=64, BK=32, 8 warps, warp tile 32x32, bf16x3 split MMA
// ---------------------------------------------------------------------------
__global__ void __launch_bounds__(256, 1) gemm1_kernel(const float* __restrict__ feat,
                                                       const float* __restrict__ feat_a,
                                                       const float* __restrict__ W1) {
    __shared__ alignas(32) __nv_bfloat16 sAh[128][48];   // BK=32 (+16 pad)
    __shared__ alignas(32) __nv_bfloat16 sAl[128][48];
    __shared__ alignas(32) __nv_bfloat16 sBh[32][80];
    __shared__ alignas(32) __nv_bfloat16 sBl[32][80];

    const int tid  = threadIdx.x;
    const int warp = tid >> 5;
    const int wm   = warp & 3;   // 4 row groups of 32
    const int wn   = warp >> 2;  // 2 col groups of 32
    const int bm0  = blockIdx.x * 128;

    wmma::fragment<wmma::accumulator, 16, 16, 16, float> acc[2][2];
#pragma unroll
    for (int i = 0; i < 2; i++)
#pragma unroll
        for (int j = 0; j < 2; j++) wmma::fill_fragment(acc[i][j], 0.0f);

#pragma unroll 1
    for (int k0 = 0; k0 < INF; k0 += 32) {
        // A tile: 128 x 32 fp32 -> bf16 hi/lo (4 float4 per thread)
#pragma unroll
        for (int it = 0; it < 4; it++) {
            int idx = tid + it * 256;          // 0..1023
            int r   = idx >> 3;                // 0..127
            int c   = (idx & 7) * 4;           // 0..28
            int gr  = bm0 + r;
            float4 v = make_float4(0.f, 0.f, 0.f, 0.f);
            if (gr < 2 * NROWS) {
                const float* src = (gr < NROWS) ? (feat + (size_t)gr * INF)
                                                : (feat_a + (size_t)(gr - NROWS) * INF);
                v = *reinterpret_cast<const float4*>(src + k0 + c);
            }
            split_store(&sAh[r][c + 0], &sAl[r][c + 0], v.x);
            split_store(&sAh[r][c + 1], &sAl[r][c + 1], v.y);
            split_store(&sAh[r][c + 2], &sAl[r][c + 2], v.z);
            split_store(&sAh[r][c + 3], &sAl[r][c + 3], v.w);
        }
        // B tile: 32 x 64 of W1 (2 float4 per thread)
#pragma unroll
        for (int it = 0; it < 2; it++) {
            int idx = tid + it * 256;          // 0..511
            int r   = idx >> 4;                // 0..31
            int c   = (idx & 15) * 4;          // 0..60
            float4 v = *reinterpret_cast<const float4*>(W1 + (size_t)(k0 + r) * OUTF + c);
            split_store(&sBh[r][c + 0], &sBl[r][c + 0], v.x);
            split_store(&sBh[r][c + 1], &sBl[r][c + 1], v.y);
            split_store(&sBh[r][c + 2], &sBl[r][c + 2], v.z);
            split_store(&sBh[r][c + 3], &sBl[r][c + 3], v.w);
        }
        __syncthreads();

#pragma unroll
        for (int kk = 0; kk < 32; kk += 16) {
            wmma::fragment<wmma::matrix_a, 16, 16, 16, __nv_bfloat16, wmma::row_major> ah[2], al[2];
            wmma::fragment<wmma::matrix_b, 16, 16, 16, __nv_bfloat16, wmma::row_major> bh[2], bl[2];
#pragma unroll
            for (int i = 0; i < 2; i++) {
                wmma::load_matrix_sync(ah[i], &sAh[wm * 32 + i * 16][kk], 48);
                wmma::load_matrix_sync(al[i], &sAl[wm * 32 + i * 16][kk], 48);
            }
#pragma unroll
            for (int j = 0; j < 2; j++) {
                wmma::load_matrix_sync(bh[j], &sBh[kk][wn * 32 + j * 16], 80);
                wmma::load_matrix_sync(bl[j], &sBl[kk][wn * 32 + j * 16], 80);
            }
#pragma unroll
            for (int i = 0; i < 2; i++)
#pragma unroll
                for (int j = 0; j < 2; j++) {
                    wmma::mma_sync(acc[i][j], ah[i], bh[j], acc[i][j]);
                    wmma::mma_sync(acc[i][j], al[i], bh[j], acc[i][j]);
                    wmma::mma_sync(acc[i][j], ah[i], bl[j], acc[i][j]);
                }
        }
        __syncthreads();
    }

    // store: each 16-row tile lies entirely in feat- or feat_a-half (20000 % 16 == 0)
#pragma unroll
    for (int i = 0; i < 2; i++) {
        int gr = bm0 + wm * 32 + i * 16;
        float* dst = (gr < NROWS) ? (g_z0 + (size_t)gr * OUTF)
                                  : (g_za0 + (size_t)(gr - NROWS) * OUTF);
#pragma unroll
        for (int j = 0; j < 2; j++)
            wmma::store_matrix_sync(dst + wn * 32 + j * 16, acc[i][j], OUTF, wmma::mem_row_major);
    }
}

// ---------------------------------------------------------------------------
// GEMM23: [20000,64] @ W2[64,1024]
//   mode==1: X = g_z0 -> mean = clip(exp), disp = clip(softplus)
//   mode==0: X = g_z2 -> h (plain store)
// BM=64, BN=64, 4 warps, K = 64 in one shot
// FIXED vs R6: A-tile smem stride is 72 (K=64 + 8 pad), was 48 -> tile overflow.
// ---------------------------------------------------------------------------
__global__ void __launch_bounds__(128, 1) gemm23_kernel(const float* __restrict__ W2,
                                                        float* __restrict__ out_h,
                                                        float* __restrict__ out_mean,
                                                        float* __restrict__ out_disp,
                                                        int mode) {
    __shared__ alignas(32) __nv_bfloat16 sAh[64][72];    // K=64 (+8 pad)
    __shared__ alignas(32) __nv_bfloat16 sAl[64][72];
    __shared__ alignas(32) __nv_bfloat16 sBh[64][80];
    __shared__ alignas(32) __nv_bfloat16 sBl[64][80];
    __shared__ alignas(32) float sStage[4][16][24];

    const float* __restrict__ X = mode ? g_z0 : g_z2;
    const int tid  = threadIdx.x;
    const int lane = tid & 31;
    const int warp = tid >> 5;
    const int wm   = warp & 1;
    const int wn   = warp >> 1;
    const int bm0  = blockIdx.y * 64;
    const int bn0  = blockIdx.x * 64;

    // A tile: 64 x 64 fp32 (8 float4 per thread)
#pragma unroll
    for (int it = 0; it < 8; it++) {
        int idx = tid + it * 128;
        int r   = idx >> 4;
        int c   = (idx & 15) * 4;
        int gr  = bm0 + r;
        float4 v = make_float4(0.f, 0.f, 0.f, 0.f);
        if (gr < NROWS) v = *reinterpret_cast<const float4*>(X + (size_t)gr * OUTF + c);
        split_store(&sAh[r][c + 0], &sAl[r][c + 0], v.x);
        split_store(&sAh[r][c + 1], &sAl[r][c + 1], v.y);
        split_store(&sAh[r][c + 2], &sAl[r][c + 2], v.z);
        split_store(&sAh[r][c + 3], &sAl[r][c + 3], v.w);
    }
    // B tile: W2 rows 0..63, cols bn0..bn0+63
#pragma unroll
    for (int it = 0; it < 8; it++) {
        int idx = tid + it * 128;
        int r   = idx >> 4;
        int c   = (idx & 15) * 4;
        float4 v = *reinterpret_cast<const float4*>(W2 + (size_t)r * INF + bn0 + c);
        split_store(&sBh[r][c + 0], &sBl[r][c + 0], v.x);
        split_store(&sBh[r][c + 1], &sBl[r][c + 1], v.y);
        split_store(&sBh[r][c + 2], &sBl[r][c + 2], v.z);
        split_store(&sBh[r][c + 3], &sBl[r][c + 3], v.w);
    }
    __syncthreads();

    wmma::fragment<wmma::accumulator, 16, 16, 16, float> acc[2][2];
#pragma unroll
    for (int i = 0; i < 2; i++)
#pragma unroll
        for (int j = 0; j < 2; j++) wmma::fill_fragment(acc[i][j], 0.0f);

#pragma unroll
    for (int kk = 0; kk < 64; kk += 16) {
        wmma::fragment<wmma::matrix_a, 16, 16, 16, __nv_bfloat16, wmma::row_major> ah[2], al[2];
        wmma::fragment<wmma::matrix_b, 16, 16, 16, __nv_bfloat16, wmma::row_major> bh[2], bl[2];
#pragma unroll
        for (int i = 0; i < 2; i++) {
            wmma::load_matrix_sync(ah[i], &sAh[wm * 32 + i * 16][kk], 72);
            wmma::load_matrix_sync(al[i], &sAl[wm * 32 + i * 16][kk], 72);
        }
#pragma unroll
        for (int j = 0; j < 2; j++) {
            wmma::load_matrix_sync(bh[j], &sBh[kk][wn * 32 + j * 16], 80);
            wmma::load_matrix_sync(bl[j], &sBl[kk][wn * 32 + j * 16], 80);
        }
#pragma unroll
        for (int i = 0; i < 2; i++)
#pragma unroll
            for (int j = 0; j < 2; j++) {
                wmma::mma_sync(acc[i][j], ah[i], bh[j], acc[i][j]);
                wmma::mma_sync(acc[i][j], al[i], bh[j], acc[i][j]);
                wmma::mma_sync(acc[i][j], ah[i], bl[j], acc[i][j]);
            }
    }

    // epilogue (tile bases are multiples of 16; 20000 % 16 == 0 -> clean guard)
#pragma unroll
    for (int i = 0; i < 2; i++) {
        int gr = bm0 + wm * 32 + i * 16;
        if (gr >= NROWS) continue;
#pragma unroll
        for (int j = 0; j < 2; j++) {
            int gc = bn0 + wn * 32 + j * 16;
            if (mode == 0) {
                wmma::store_matrix_sync(out_h + (size_t)gr * INF + gc, acc[i][j], INF,
                                        wmma::mem_row_major);
            } else {
                wmma::store_matrix_sync(&sStage[warp][0][0], acc[i][j], 24, wmma::mem_row_major);
                __syncwarp();
                for (int t = lane; t < 256; t += 32) {
                    int rr = t >> 4, cc = t & 15;
                    float x  = sStage[warp][rr][cc];
                    float m  = fminf(fmaxf(expf(x), 1e-5f), 1e6f);
                    float sp = fmaxf(x, 0.f) + log1pf(expf(-fabsf(x)));
                    sp = fminf(fmaxf(sp, 1e-4f), 1e4f);
                    size_t o = (size_t)(gr + rr) * INF + gc + cc;
                    out_mean[o] = m;
                    out_disp[o] = sp;
                }
                __syncwarp();
            }
        }
    }
}

// ---------------------------------------------------------------------------
// SpMM (COO scatter): dst[row[e]] += vals[e] * src[col[e]]  over 64 columns.
// Half-warp per edge, one float4 vector atomic per lane. All operands L2-resident.
// src_sel: 0=g_z0, 1=g_za0, 2=z(d_out)  dst_sel: 0=z(d_out), 1=g_sa, 2=g_ss, 3=g_z2
// ---------------------------------------------------------------------------
__global__ void __launch_bounds__(256) spmm_kernel(const int* __restrict__ row,
                                                   const int* __restrict__ col,
                                                   const float* __restrict__ vals,
                                                   int src_sel, int dst_sel,
                                                   float* __restrict__ z_out, int nnz) {
    const float* src = (src_sel == 0) ? g_z0 : ((src_sel == 1) ? g_za0 : z_out);
    float* dst = (dst_sel == 0) ? z_out : ((dst_sel == 1) ? g_sa : ((dst_sel == 2) ? g_ss : g_z2));

    long gid = (long)blockIdx.x * 256 + threadIdx.x;
    long e   = gid >> 4;
    int  j   = (int)(gid & 15);
    if (e >= nnz) return;

    int   c = __ldg(col + e);
    int   r = __ldg(row + e);
    float v = __ldg(vals + e);

    float4 x = *reinterpret_cast<const float4*>(src + (size_t)c * OUTF + j * 4);
    float4 y = make_float4(x.x * v, x.y * v, x.z * v, x.w * v);
    atomicAdd(reinterpret_cast<float4*>(dst + (size_t)r * OUTF + j * 4), y);
}

// ---------------------------------------------------------------------------
// Discriminator: ret[n]   = relu(sa[n])^T W relu(z[n])   + b
//                ret_a[n] = relu(ss[n])^T W relu(sa[n])  + b
// One warp per row; W (64x64) staged in smem once per block.
// ---------------------------------------------------------------------------
__global__ void __launch_bounds__(256) disc_kernel(const float* __restrict__ z,
                                                   const float* __restrict__ dW,
                                                   const float* __restrict__ db,
                                                   float* __restrict__ ret,
                                                   float* __restrict__ ret_a) {
    __shared__ float sW[64][65];
    __shared__ float sV[8][3][64];

    const int tid  = threadIdx.x;
    const int lane = tid & 31;
    const int warp = tid >> 5;

    for (int i = tid; i < 64 * 64; i += 256) sW[i >> 6][i & 63] = dW[i];
    __syncthreads();
    const float b = __ldg(db);

    for (int n = blockIdx.x * 8 + warp; n < NROWS; n += gridDim.x * 8) {
#pragma unroll
        for (int t = lane; t < 64; t += 32) {
            size_t o = (size_t)n * OUTF + t;
            sV[warp][0][t] = fmaxf(z[o], 0.f);      // emb
            sV[warp][1][t] = fmaxf(g_sa[o], 0.f);   // emb_a
            sV[warp][2][t] = fmaxf(g_ss[o], 0.f);   // emb_s
        }
        __syncwarp();

        float acc1 = 0.f, acc2 = 0.f;
#pragma unroll
        for (int kb = 0; kb < 2; kb++) {
            int k = lane + kb * 32;
            float t1 = 0.f, t2 = 0.f;
#pragma unroll 16
            for (int d = 0; d < 64; d++) {
                float w = sW[d][k];
                t1 = fmaf(sV[warp][1][d], w, t1);   // sum_d emb_a[d] W[d][k]
                t2 = fmaf(sV[warp][2][d], w, t2);   // sum_d emb_s[d] W[d][k]
            }
            acc1 = fmaf(sV[warp][0][k], t1, acc1);  // * emb[k]
            acc2 = fmaf(sV[warp][1][k], t2, acc2);  // * emb_a[k]
        }
#pragma unroll
        for (int o = 16; o; o >>= 1) {
            acc1 += __shfl_xor_sync(0xffffffffu, acc1, o);
            acc2 += __shfl_xor_sync(0xffffffffu, acc2, o);
        }
        if (lane == 0) {
            ret[n]   = acc1 + b;
            ret_a[n] = acc2 + b;
        }
        __syncwarp();
    }
}

// ---------------------------------------------------------------------------
// kernel_launch
// Output layout (flattened tuple): hiden_emb[N,64] | h[N,1024] | ret[N,1] |
//                                  ret_a[N,1] | mean[N,1024] | disp[N,1024]
// ---------------------------------------------------------------------------
extern "C" void kernel_launch(void* const* d_in, const int* in_sizes, int n_in,
                              void* d_out, int out_size) {
    const float* feat   = (const float*)d_in[0];
    const float* feat_a = (const float*)d_in[1];
    const int*   row    = (const int*)d_in[2];
    const int*   col    = (const int*)d_in[3];
    const float* vals   = (const float*)d_in[4];
    const int*   row_a  = (const int*)d_in[5];
    const int*   col_a  = (const int*)d_in[6];
    const float* vals_a = (const float*)d_in[7];
    const float* W1     = (const float*)d_in[8];
    const float* W2     = (const float*)d_in[9];
    const float* dW     = (const float*)d_in[10];
    const float* db     = (const float*)d_in[11];

    float* out   = (float*)d_out;
    float* z_out = out;                                 // hiden_emb (= z, scattered here)
    float* h_out = z_out + (size_t)NROWS * OUTF;
    float* ret   = h_out + (size_t)NROWS * INF;
    float* ret_a = ret + NROWS;
    float* mean  = ret_a + NROWS;
    float* disp  = mean + (size_t)NROWS * INF;

    const int nnz         = in_sizes[2];
    const int zero_blocks = ((NROWS * OUTF) / 4 + 255) / 256;
    const int spmm_blocks = (int)(((long)nnz * 16 + 255) / 256);
    const int g1_blocks   = (2 * NROWS + 127) / 128;    // 313

    // 1. zero atomic-scatter destinations (z region of d_out, sa, ss, z2)
    zero_kernel<<<zero_blocks, 256>>>(z_out);
    // 2. z0 = feat @ W1 ; za0 = feat_a @ W1  (single fused GEMM, bf16x3 split)
    gemm1_kernel<<<g1_blocks, 256>>>(feat, feat_a, W1);
    // 3. z = A z0 -> d_out (hiden_emb) ; sa = A za0 ; ss = Aa za0
    spmm_kernel<<<spmm_blocks, 256>>>(row, col, vals, 0, 0, z_out, nnz);
    spmm_kernel<<<spmm_blocks, 256>>>(row, col, vals, 1, 1, z_out, nnz);
    spmm_kernel<<<spmm_blocks, 256>>>(row_a, col_a, vals_a, 1, 2, z_out, nnz);
    // 4. zinb = z0 @ W2 -> mean/disp (fused epilogue)
    gemm23_kernel<<<dim3(INF / 64, (NROWS + 63) / 64), 128>>>(W2, h_out, mean, disp, 1);
    // 5. z2 = A z  (uses z in d_out)
    spmm_kernel<<<spmm_blocks, 256>>>(row, col, vals, 2, 3, z_out, nnz);
    // 6. h = z2 @ W2   [= A (z @ W2) by associativity]
    gemm23_kernel<<<dim3(INF / 64, (NROWS + 63) / 64), 128>>>(W2, h_out, mean, disp, 0);
    // 7. bilinear discriminator heads
    disc_kernel<<<296, 256>>>(z_out, dW, db, ret, ret_a);
}

// round 9
// speedup vs baseline: 1.3430x; 1.3430x over previous
#include <cuda_runtime.h>
#include <cuda_bf16.h>
#include <mma.h>
#include <math.h>

using namespace nvcuda;

// Problem constants (fixed by the dataset)
#define NROWS 20000
#define INF   1024
#define OUTF  64

// ---------------------------------------------------------------------------
// Scratch (device globals; no runtime allocation allowed)
// ---------------------------------------------------------------------------
__device__ alignas(256) float g_z0 [NROWS * OUTF];          // feat   @ W1
__device__ alignas(256) float g_za0[20064 * OUTF];          // feat_a @ W1 (padded: gemm1 tail rows)
__device__ alignas(256) float g_z2 [NROWS * OUTF];          // spmm(A, z)
__device__ alignas(256) float g_sa [NROWS * OUTF];          // spmm(A,  za0)
__device__ alignas(256) float g_ss [NROWS * OUTF];          // spmm(Aa, za0)

// ---------------------------------------------------------------------------
// fp32 -> bf16 hi/lo split helpers (error-compensated tensor-core GEMM)
// ---------------------------------------------------------------------------
__device__ __forceinline__ void split_store(__nv_bfloat16* hi, __nv_bfloat16* lo, float x) {
    __nv_bfloat16 h = __float2bfloat16(x);
    *hi = h;
    *lo = __float2bfloat16(x - __bfloat162float(h));
}

// packed pair: one 32-bit STS for hi, one for lo
__device__ __forceinline__ void split_store2(__nv_bfloat16* hiPtr, __nv_bfloat16* loPtr,
                                             float x, float y) {
    __nv_bfloat162 h = __floats2bfloat162_rn(x, y);
    *reinterpret_cast<__nv_bfloat162*>(hiPtr) = h;
    float rx = x - __bfloat162float(__low2bfloat16(h));
    float ry = y - __bfloat162float(__high2bfloat16(h));
    *reinterpret_cast<__nv_bfloat162*>(loPtr) = __floats2bfloat162_rn(rx, ry);
}

__device__ __forceinline__ void split_store_f4(__nv_bfloat16* hi, __nv_bfloat16* lo, float4 v) {
    split_store2(hi + 0, lo + 0, v.x, v.y);
    split_store2(hi + 2, lo + 2, v.z, v.w);
}

// ---------------------------------------------------------------------------
// zero scratch that receives atomic scatter (+ z region of d_out)
// ---------------------------------------------------------------------------
__global__ void __launch_bounds__(256) zero_kernel(float* __restrict__ z_out) {
    int i = blockIdx.x * 256 + threadIdx.x;            // over 320000 float4 per array
    if (i < (NROWS * OUTF) / 4) {
        float4 z = make_float4(0.f, 0.f, 0.f, 0.f);
        reinterpret_cast<float4*>(z_out)[i] = z;
        reinterpret_cast<float4*>(g_sa)[i]  = z;
        reinterpret_cast<float4*>(g_ss)[i]  = z;
        reinterpret_cast<float4*>(g_z2)[i]  = z;
    }
}

// ---------------------------------------------------------------------------
// GEMM1: [40000,1024] @ [1024,64] -> z0 / za0
// BM=128, BN=64, BK=32, 8 warps, warp tile 32x32, bf16x3 split MMA.
// Register-prefetch pipeline: next K-tile's global loads are issued before the
// current tile's MMAs so DRAM latency overlaps tensor work.
// ---------------------------------------------------------------------------
__global__ void __launch_bounds__(256) gemm1_kernel(const float* __restrict__ feat,
                                                    const float* __restrict__ feat_a,
                                                    const float* __restrict__ W1) {
    __shared__ alignas(32) __nv_bfloat16 sAh[128][48];   // BK=32 (+16 pad)
    __shared__ alignas(32) __nv_bfloat16 sAl[128][48];
    __shared__ alignas(32) __nv_bfloat16 sBh[32][80];
    __shared__ alignas(32) __nv_bfloat16 sBl[32][80];

    const int tid  = threadIdx.x;
    const int warp = tid >> 5;
    const int wm   = warp & 3;   // 4 row groups of 32
    const int wn   = warp >> 2;  // 2 col groups of 32
    const int bm0  = blockIdx.x * 128;

    // per-thread tile coordinates (fixed across iterations)
    const int ar0 = (tid * 4 + 0 * 1024) >> 5;   // not used; explicit below
    (void)ar0;

    wmma::fragment<wmma::accumulator, 16, 16, 16, float> acc[2][2];
#pragma unroll
    for (int i = 0; i < 2; i++)
#pragma unroll
        for (int j = 0; j < 2; j++) wmma::fill_fragment(acc[i][j], 0.0f);

    float4 aReg[4];
    float4 bReg[2];

    auto prefetch = [&](int k0) {
#pragma unroll
        for (int it = 0; it < 4; it++) {
            int idx = tid + it * 256;          // 0..1023
            int r   = idx >> 3;                // 0..127
            int c   = (idx & 7) * 4;           // 0..28
            int gr  = bm0 + r;
            float4 v = make_float4(0.f, 0.f, 0.f, 0.f);
            if (gr < 2 * NROWS) {
                const float* src = (gr < NROWS) ? (feat + (size_t)gr * INF)
                                                : (feat_a + (size_t)(gr - NROWS) * INF);
                v = *reinterpret_cast<const float4*>(src + k0 + c);
            }
            aReg[it] = v;
        }
#pragma unroll
        for (int it = 0; it < 2; it++) {
            int idx = tid + it * 256;          // 0..511
            int r   = idx >> 4;                // 0..31
            int c   = (idx & 15) * 4;          // 0..60
            bReg[it] = *reinterpret_cast<const float4*>(W1 + (size_t)(k0 + r) * OUTF + c);
        }
    };

    prefetch(0);

#pragma unroll 1
    for (int k0 = 0; k0 < INF; k0 += 32) {
        // commit prefetched registers to smem (bf16 hi/lo, packed stores)
#pragma unroll
        for (int it = 0; it < 4; it++) {
            int idx = tid + it * 256;
            int r   = idx >> 3;
            int c   = (idx & 7) * 4;
            split_store_f4(&sAh[r][c], &sAl[r][c], aReg[it]);
        }
#pragma unroll
        for (int it = 0; it < 2; it++) {
            int idx = tid + it * 256;
            int r   = idx >> 4;
            int c   = (idx & 15) * 4;
            split_store_f4(&sBh[r][c], &sBl[r][c], bReg[it]);
        }
        __syncthreads();

        // issue next tile's global loads NOW (latency overlaps MMAs below)
        if (k0 + 32 < INF) prefetch(k0 + 32);

#pragma unroll
        for (int kk = 0; kk < 32; kk += 16) {
            wmma::fragment<wmma::matrix_a, 16, 16, 16, __nv_bfloat16, wmma::row_major> ah[2], al[2];
            wmma::fragment<wmma::matrix_b, 16, 16, 16, __nv_bfloat16, wmma::row_major> bh[2], bl[2];
#pragma unroll
            for (int i = 0; i < 2; i++) {
                wmma::load_matrix_sync(ah[i], &sAh[wm * 32 + i * 16][kk], 48);
                wmma::load_matrix_sync(al[i], &sAl[wm * 32 + i * 16][kk], 48);
            }
#pragma unroll
            for (int j = 0; j < 2; j++) {
                wmma::load_matrix_sync(bh[j], &sBh[kk][wn * 32 + j * 16], 80);
                wmma::load_matrix_sync(bl[j], &sBl[kk][wn * 32 + j * 16], 80);
            }
#pragma unroll
            for (int i = 0; i < 2; i++)
#pragma unroll
                for (int j = 0; j < 2; j++) {
                    wmma::mma_sync(acc[i][j], ah[i], bh[j], acc[i][j]);
                    wmma::mma_sync(acc[i][j], al[i], bh[j], acc[i][j]);
                    wmma::mma_sync(acc[i][j], ah[i], bl[j], acc[i][j]);
                }
        }
        __syncthreads();
    }

    // store: each 16-row tile lies entirely in feat- or feat_a-half (20000 % 16 == 0)
#pragma unroll
    for (int i = 0; i < 2; i++) {
        int gr = bm0 + wm * 32 + i * 16;
        float* dst = (gr < NROWS) ? (g_z0 + (size_t)gr * OUTF)
                                  : (g_za0 + (size_t)(gr - NROWS) * OUTF);
#pragma unroll
        for (int j = 0; j < 2; j++)
            wmma::store_matrix_sync(dst + wn * 32 + j * 16, acc[i][j], OUTF, wmma::mem_row_major);
    }
}

// ---------------------------------------------------------------------------
// Fused GEMM23: both products against the shared W2 tile in one pass.
//   phase 1: z0 @ W2 -> mean = clip(exp), disp = clip(softplus)
//   phase 2: z2 @ W2 -> h (plain store)
// BM=64, BN=64, 4 warps, K=64 in one shot. Dynamic smem (62 KB).
// ---------------------------------------------------------------------------
__global__ void __launch_bounds__(128) gemm23_fused_kernel(const float* __restrict__ W2,
                                                           float* __restrict__ out_h,
                                                           float* __restrict__ out_mean,
                                                           float* __restrict__ out_disp) {
    extern __shared__ char smemRaw[];
    __nv_bfloat16* sA1h = reinterpret_cast<__nv_bfloat16*>(smemRaw);      // [64][72]
    __nv_bfloat16* sA1l = sA1h + 64 * 72;
    __nv_bfloat16* sA2h = sA1l + 64 * 72;
    __nv_bfloat16* sA2l = sA2h + 64 * 72;
    __nv_bfloat16* sBh  = sA2l + 64 * 72;                                 // [64][80]
    __nv_bfloat16* sBl  = sBh + 64 * 80;
    float*         sStage = reinterpret_cast<float*>(sBl + 64 * 80);      // [4][16][24]

    const int tid  = threadIdx.x;
    const int lane = tid & 31;
    const int warp = tid >> 5;
    const int wm   = warp & 1;
    const int wn   = warp >> 1;
    const int bm0  = blockIdx.y * 64;
    const int bn0  = blockIdx.x * 64;

    // A tiles: 64 x 64 fp32 from g_z0 and g_z2 (8 float4 per thread each)
#pragma unroll
    for (int it = 0; it < 8; it++) {
        int idx = tid + it * 128;
        int r   = idx >> 4;
        int c   = (idx & 15) * 4;
        int gr  = bm0 + r;
        float4 v1 = make_float4(0.f, 0.f, 0.f, 0.f);
        float4 v2 = v1;
        if (gr < NROWS) {
            v1 = *reinterpret_cast<const float4*>(g_z0 + (size_t)gr * OUTF + c);
            v2 = *reinterpret_cast<const float4*>(g_z2 + (size_t)gr * OUTF + c);
        }
        split_store_f4(&sA1h[r * 72 + c], &sA1l[r * 72 + c], v1);
        split_store_f4(&sA2h[r * 72 + c], &sA2l[r * 72 + c], v2);
    }
    // B tile: W2 rows 0..63, cols bn0..bn0+63
#pragma unroll
    for (int it = 0; it < 8; it++) {
        int idx = tid + it * 128;
        int r   = idx >> 4;
        int c   = (idx & 15) * 4;
        float4 v = *reinterpret_cast<const float4*>(W2 + (size_t)r * INF + bn0 + c);
        split_store_f4(&sBh[r * 80 + c], &sBl[r * 80 + c], v);
    }
    __syncthreads();

    // two phases over the same B tile; acc registers reused sequentially
#pragma unroll 1
    for (int phase = 0; phase < 2; phase++) {
        const __nv_bfloat16* Ah = phase ? sA2h : sA1h;
        const __nv_bfloat16* Al = phase ? sA2l : sA1l;

        wmma::fragment<wmma::accumulator, 16, 16, 16, float> acc[2][2];
#pragma unroll
        for (int i = 0; i < 2; i++)
#pragma unroll
            for (int j = 0; j < 2; j++) wmma::fill_fragment(acc[i][j], 0.0f);

#pragma unroll
        for (int kk = 0; kk < 64; kk += 16) {
            wmma::fragment<wmma::matrix_a, 16, 16, 16, __nv_bfloat16, wmma::row_major> ah[2], al[2];
            wmma::fragment<wmma::matrix_b, 16, 16, 16, __nv_bfloat16, wmma::row_major> bh[2], bl[2];
#pragma unroll
            for (int i = 0; i < 2; i++) {
                wmma::load_matrix_sync(ah[i], Ah + (wm * 32 + i * 16) * 72 + kk, 72);
                wmma::load_matrix_sync(al[i], Al + (wm * 32 + i * 16) * 72 + kk, 72);
            }
#pragma unroll
            for (int j = 0; j < 2; j++) {
                wmma::load_matrix_sync(bh[j], sBh + kk * 80 + wn * 32 + j * 16, 80);
                wmma::load_matrix_sync(bl[j], sBl + kk * 80 + wn * 32 + j * 16, 80);
            }
#pragma unroll
            for (int i = 0; i < 2; i++)
#pragma unroll
                for (int j = 0; j < 2; j++) {
                    wmma::mma_sync(acc[i][j], ah[i], bh[j], acc[i][j]);
                    wmma::mma_sync(acc[i][j], al[i], bh[j], acc[i][j]);
                    wmma::mma_sync(acc[i][j], ah[i], bl[j], acc[i][j]);
                }
        }

        // epilogue
#pragma unroll
        for (int i = 0; i < 2; i++) {
            int gr = bm0 + wm * 32 + i * 16;
            if (gr >= NROWS) continue;
#pragma unroll
            for (int j = 0; j < 2; j++) {
                int gc = bn0 + wn * 32 + j * 16;
                if (phase == 1) {
                    wmma::store_matrix_sync(out_h + (size_t)gr * INF + gc, acc[i][j], INF,
                                            wmma::mem_row_major);
                } else {
                    float* st = sStage + warp * 16 * 24;
                    wmma::store_matrix_sync(st, acc[i][j], 24, wmma::mem_row_major);
                    __syncwarp();
                    for (int t = lane; t < 256; t += 32) {
                        int rr = t >> 4, cc = t & 15;
                        float x  = st[rr * 24 + cc];
                        float m  = fminf(fmaxf(expf(x), 1e-5f), 1e6f);
                        float sp = fmaxf(x, 0.f) + log1pf(expf(-fabsf(x)));
                        sp = fminf(fmaxf(sp, 1e-4f), 1e4f);
                        size_t o = (size_t)(gr + rr) * INF + gc + cc;
                        out_mean[o] = m;
                        out_disp[o] = sp;
                    }
                    __syncwarp();
                }
            }
        }
    }
}

// ---------------------------------------------------------------------------
// Fused SpMM for the three independent scatters:
//   A-edges  (t in [0,nnz)):   z  += v * z0[col]   AND   sa += v * za0[col]
//   Aa-edges (t in [nnz,nnz+nnz_a)):                    ss += v * za0[col_a]
// Half-warp (16 lanes) per edge, one float4 vector atomic per lane per output.
// ---------------------------------------------------------------------------
__global__ void __launch_bounds__(256) spmm3_kernel(const int* __restrict__ row,
                                                    const int* __restrict__ col,
                                                    const float* __restrict__ vals,
                                                    const int* __restrict__ row_a,
                                                    const int* __restrict__ col_a,
                                                    const float* __restrict__ vals_a,
                                                    float* __restrict__ z_out,
                                                    int nnz, int nnz_a) {
    long gid = (long)blockIdx.x * 256 + threadIdx.x;
    long t   = gid >> 4;
    int  j   = (int)(gid & 15) * 4;

    if (t < nnz) {
        int   c = __ldg(col + t);
        int   r = __ldg(row + t);
        float v = __ldg(vals + t);
        float4 x0 = *reinterpret_cast<const float4*>(g_z0 + (size_t)c * OUTF + j);
        atomicAdd(reinterpret_cast<float4*>(z_out + (size_t)r * OUTF + j),
                  make_float4(x0.x * v, x0.y * v, x0.z * v, x0.w * v));
        float4 xa = *reinterpret_cast<const float4*>(g_za0 + (size_t)c * OUTF + j);
        atomicAdd(reinterpret_cast<float4*>(g_sa + (size_t)r * OUTF + j),
                  make_float4(xa.x * v, xa.y * v, xa.z * v, xa.w * v));
    } else {
        long e = t - nnz;
        if (e < nnz_a) {
            int   c = __ldg(col_a + e);
            int   r = __ldg(row_a + e);
            float v = __ldg(vals_a + e);
            float4 xa = *reinterpret_cast<const float4*>(g_za0 + (size_t)c * OUTF + j);
            atomicAdd(reinterpret_cast<float4*>(g_ss + (size_t)r * OUTF + j),
                      make_float4(xa.x * v, xa.y * v, xa.z * v, xa.w * v));
        }
    }
}

// ---------------------------------------------------------------------------
// SpMM4: z2 += vals[e] * z[col[e]]   (z lives in d_out)
// ---------------------------------------------------------------------------
__global__ void __launch_bounds__(256) spmm4_kernel(const int* __restrict__ row,
                                                    const int* __restrict__ col,
                                                    const float* __restrict__ vals,
                                                    const float* __restrict__ z_in,
                                                    int nnz) {
    long gid = (long)blockIdx.x * 256 + threadIdx.x;
    long e   = gid >> 4;
    int  j   = (int)(gid & 15) * 4;
    if (e >= nnz) return;

    int   c = __ldg(col + e);
    int   r = __ldg(row + e);
    float v = __ldg(vals + e);
    float4 x = *reinterpret_cast<const float4*>(z_in + (size_t)c * OUTF + j);
    atomicAdd(reinterpret_cast<float4*>(g_z2 + (size_t)r * OUTF + j),
              make_float4(x.x * v, x.y * v, x.z * v, x.w * v));
}

// ---------------------------------------------------------------------------
// Discriminator: ret[n]   = relu(sa[n])^T W relu(z[n])   + b
//                ret_a[n] = relu(ss[n])^T W relu(sa[n])  + b
// ---------------------------------------------------------------------------
__global__ void __launch_bounds__(256) disc_kernel(const float* __restrict__ z,
                                                   const float* __restrict__ dW,
                                                   const float* __restrict__ db,
                                                   float* __restrict__ ret,
                                                   float* __restrict__ ret_a) {
    __shared__ float sW[64][65];
    __shared__ float sV[8][3][64];

    const int tid  = threadIdx.x;
    const int lane = tid & 31;
    const int warp = tid >> 5;

    for (int i = tid; i < 64 * 64; i += 256) sW[i >> 6][i & 63] = dW[i];
    __syncthreads();
    const float b = __ldg(db);

    for (int n = blockIdx.x * 8 + warp; n < NROWS; n += gridDim.x * 8) {
#pragma unroll
        for (int t = lane; t < 64; t += 32) {
            size_t o = (size_t)n * OUTF + t;
            sV[warp][0][t] = fmaxf(z[o], 0.f);      // emb
            sV[warp][1][t] = fmaxf(g_sa[o], 0.f);   // emb_a
            sV[warp][2][t] = fmaxf(g_ss[o], 0.f);   // emb_s
        }
        __syncwarp();

        float acc1 = 0.f, acc2 = 0.f;
#pragma unroll
        for (int kb = 0; kb < 2; kb++) {
            int k = lane + kb * 32;
            float t1 = 0.f, t2 = 0.f;
#pragma unroll 16
            for (int d = 0; d < 64; d++) {
                float w = sW[d][k];
                t1 = fmaf(sV[warp][1][d], w, t1);   // sum_d emb_a[d] W[d][k]
                t2 = fmaf(sV[warp][2][d], w, t2);   // sum_d emb_s[d] W[d][k]
            }
            acc1 = fmaf(sV[warp][0][k], t1, acc1);  // * emb[k]
            acc2 = fmaf(sV[warp][1][k], t2, acc2);  // * emb_a[k]
        }
#pragma unroll
        for (int o = 16; o; o >>= 1) {
            acc1 += __shfl_xor_sync(0xffffffffu, acc1, o);
            acc2 += __shfl_xor_sync(0xffffffffu, acc2, o);
        }
        if (lane == 0) {
            ret[n]   = acc1 + b;
            ret_a[n] = acc2 + b;
        }
        __syncwarp();
    }
}

// ---------------------------------------------------------------------------
// kernel_launch
// Output layout (flattened tuple): hiden_emb[N,64] | h[N,1024] | ret[N,1] |
//                                  ret_a[N,1] | mean[N,1024] | disp[N,1024]
// ---------------------------------------------------------------------------
extern "C" void kernel_launch(void* const* d_in, const int* in_sizes, int n_in,
                              void* d_out, int out_size) {
    const float* feat   = (const float*)d_in[0];
    const float* feat_a = (const float*)d_in[1];
    const int*   row    = (const int*)d_in[2];
    const int*   col    = (const int*)d_in[3];
    const float* vals   = (const float*)d_in[4];
    const int*   row_a  = (const int*)d_in[5];
    const int*   col_a  = (const int*)d_in[6];
    const float* vals_a = (const float*)d_in[7];
    const float* W1     = (const float*)d_in[8];
    const float* W2     = (const float*)d_in[9];
    const float* dW     = (const float*)d_in[10];
    const float* db     = (const float*)d_in[11];

    float* out   = (float*)d_out;
    float* z_out = out;                                 // hiden_emb (= z, scattered here)
    float* h_out = z_out + (size_t)NROWS * OUTF;
    float* ret   = h_out + (size_t)NROWS * INF;
    float* ret_a = ret + NROWS;
    float* mean  = ret_a + NROWS;
    float* disp  = mean + (size_t)NROWS * INF;

    const int nnz   = in_sizes[2];
    const int nnz_a = in_sizes[5];

    const int zero_blocks  = ((NROWS * OUTF) / 4 + 255) / 256;
    const int spmm3_blocks = (int)((((long)nnz + nnz_a) * 16 + 255) / 256);
    const int spmm4_blocks = (int)(((long)nnz * 16 + 255) / 256);
    const int g1_blocks    = (2 * NROWS + 127) / 128;   // 313

    const int fusedSmem = (4 * 64 * 72 + 2 * 64 * 80) * 2 + 4 * 16 * 24 * 4;  // 63488 B
    cudaFuncSetAttribute(gemm23_fused_kernel,
                         cudaFuncAttributeMaxDynamicSharedMemorySize, fusedSmem);

    // 1. zero atomic-scatter destinations (z region of d_out, sa, ss, z2)
    zero_kernel<<<zero_blocks, 256>>>(z_out);
    // 2. z0 = feat @ W1 ; za0 = feat_a @ W1  (single fused GEMM, pipelined bf16x3)
    gemm1_kernel<<<g1_blocks, 256>>>(feat, feat_a, W1);
    // 3. fused scatters: z = A z0 -> d_out ; sa = A za0 ; ss = Aa za0
    spmm3_kernel<<<spmm3_blocks, 256>>>(row, col, vals, row_a, col_a, vals_a,
                                        z_out, nnz, nnz_a);
    // 4. z2 = A z  (uses z in d_out)
    spmm4_kernel<<<spmm4_blocks, 256>>>(row, col, vals, z_out, nnz);
    // 5. fused GEMM: mean/disp = f(z0 @ W2)  and  h = z2 @ W2 (= A(zW2))
    gemm23_fused_kernel<<<dim3(INF / 64, (NROWS + 63) / 64), 128, fusedSmem>>>(
        W2, h_out, mean, disp);
    // 6. bilinear discriminator heads
    disc_kernel<<<296, 256>>>(z_out, dW, db, ret, ret_a);
}